// round 6
// baseline (speedup 1.0000x reference)
#include <cuda_runtime.h>
#include <cuda_bf16.h>
#include <cstdint>
#include <math.h>

#define BB 8192
#define DD 512
#define CC 80
#define MARGIN 0.3f

#define BM 128
#define NTILE (BB / BM)                  // 64
#define NTRI  (NTILE * (NTILE + 1) / 2)  // 2080
#define BK 32                            // tf32 K-chunk
#define NCH (DD / BK)                    // 16

// smem layout (floats / bytes)
#define RS    36                         // padded row stride in floats (32+4)
#define OPB   (128 * RS * 4)             // 18432 B per operand tile
#define BUFB  (2 * OPB)                  // 36864 B per buffer (A,B)
#define SM_SQI 73728
#define SM_SQJ 74240
#define SM_MI  74752
#define SM_MJ  76800
#define SM_TOT 78848                     // sD[128*129*4B]=66048 overlays buffers

// ---- device scratch ----
__device__ uint32_t g_et[(size_t)BB * DD];     // tf32-rounded normalized embeddings
__device__ float g_sq[BB];
__device__ ulonglong2 g_m[BB];
__device__ int g_si[BB];
__device__ float g_dist[(size_t)BB * BB];
__device__ unsigned g_hardneg[BB];
__device__ float g_loss_sum;
__device__ float g_valid_cnt;

// ---- PTX helpers (baseline ISA only) ----
__device__ __forceinline__ uint32_t smem_u32(const void* p) {
    uint32_t a;
    asm("{ .reg .u64 t; cvta.to.shared.u64 t, %1; cvt.u32.u64 %0, t; }" : "=r"(a) : "l"(p));
    return a;
}
#define CP_ASYNC16(dst, src) \
    asm volatile("cp.async.cg.shared.global [%0], [%1], 16;" :: "r"(dst), "l"(src))
#define CP_COMMIT() asm volatile("cp.async.commit_group;" ::: "memory")
#define CP_WAIT1()  asm volatile("cp.async.wait_group 1;" ::: "memory")
#define CP_WAIT0()  asm volatile("cp.async.wait_group 0;" ::: "memory")

#define MMA1688(d, a, b) \
    asm volatile("mma.sync.aligned.m16n8k8.row.col.f32.tf32.tf32.f32 " \
        "{%0,%1,%2,%3}, {%4,%5,%6,%7}, {%8,%9}, {%0,%1,%2,%3};" \
        : "+f"((d)[0]), "+f"((d)[1]), "+f"((d)[2]), "+f"((d)[3]) \
        : "r"((a)[0]), "r"((a)[1]), "r"((a)[2]), "r"((a)[3]), "r"((b)[0]), "r"((b)[1]))

__device__ __forceinline__ uint32_t f2tf32(float x) {
    uint32_t u;
    asm("cvt.rna.tf32.f32 %0, %1;" : "=r"(u) : "f"(x));
    return u;
}

// ---- 1) reset accumulators + label bitmasks ----
__global__ void prep_kernel(const float* __restrict__ labels) {
    int i = blockIdx.x * blockDim.x + threadIdx.x;
    if (i == 0) { g_loss_sum = 0.f; g_valid_cnt = 0.f; }
    if (i < BB) {
        const float* lr = labels + (size_t)i * CC;
        unsigned long long m0 = 0ull, m1 = 0ull;
        #pragma unroll
        for (int c = 0; c < 64; c++)
            if (lr[c] != 0.f) m0 |= (1ull << c);
        #pragma unroll
        for (int c = 64; c < CC; c++)
            if (lr[c] != 0.f) m1 |= (1ull << (c - 64));
        g_m[i] = make_ulonglong2(m0, m1);
        g_si[i] = __popcll(m0) + __popcll(m1);
        g_hardneg[i] = __float_as_uint(1e9f);
    }
}

// ---- 2) normalize + tf32 round ----
__global__ __launch_bounds__(128) void normalize_kernel(const float* __restrict__ emb) {
    int row = blockIdx.x;
    int t = threadIdx.x;
    const float4* in = (const float4*)(emb + (size_t)row * DD);
    float4 v = in[t];
    float ss = v.x * v.x + v.y * v.y + v.z * v.z + v.w * v.w;
    #pragma unroll
    for (int o = 16; o > 0; o >>= 1) ss += __shfl_xor_sync(0xFFFFFFFFu, ss, o);
    __shared__ float red[4];
    if ((t & 31) == 0) red[t >> 5] = ss;
    __syncthreads();
    float tot = red[0] + red[1] + red[2] + red[3];
    float inv = 1.f / fmaxf(sqrtf(tot), 1e-12f);
    uint4 o4;
    o4.x = f2tf32(v.x * inv);
    o4.y = f2tf32(v.y * inv);
    o4.z = f2tf32(v.z * inv);
    o4.w = f2tf32(v.w * inv);
    *(uint4*)(g_et + (size_t)row * DD + t * 4) = o4;
    if (t == 0) g_sq[row] = tot * inv * inv;
}

// ---- 3) tf32 mma.sync Gram GEMM over triangular tiles + fused epilogue ----
__global__ __launch_bounds__(256, 2) void gemm_tc_kernel() {
    extern __shared__ __align__(1024) char smem[];
    const uint32_t sb = smem_u32(smem);
    const int tid = threadIdx.x;
    const int wid = tid >> 5;
    const int lane = tid & 31;
    const int wm = wid >> 2;         // 0..1 -> rows wm*64
    const int wn = wid & 3;          // 0..3 -> cols wn*32

    // triangular tile map (by <= bx)
    const int t = blockIdx.x;
    int p = (int)((sqrt(8.0 * t + 1.0) - 1.0) * 0.5);
    while ((p * (p + 1)) / 2 > t) p--;
    while (((p + 1) * (p + 2)) / 2 <= t) p++;
    const int bx = p;
    const int by = t - (p * (p + 1)) / 2;
    const bool diag = (bx == by);

    // stage per-row/col metadata (region disjoint from pipeline buffers)
    if (tid < 128) {
        int gi = by * BM + tid, gj = bx * BM + tid;
        ((float*)(smem + SM_SQI))[tid] = g_sq[gi];
        ((float*)(smem + SM_SQJ))[tid] = g_sq[gj];
        ((ulonglong2*)(smem + SM_MI))[tid] = g_m[gi];
        ((ulonglong2*)(smem + SM_MJ))[tid] = g_m[gj];
    }

    // loader: threads 0-127 -> A rows, 128-255 -> B rows; 8 x 16B per row-chunk
    const int lrow = tid & 127;
    const int lop = tid >> 7;                    // 0=A, 1=B
    const char* src_row = (const char*)(g_et + (size_t)(((lop ? bx : by) * BM) + lrow) * DD);

    auto load_chunk = [&](int c, int buf) {
        uint32_t dst = sb + buf * BUFB + lop * OPB + lrow * (RS * 4);
        const char* src = src_row + c * (BK * 4);
        #pragma unroll
        for (int s = 0; s < 8; s++)
            CP_ASYNC16(dst + s * 16, src + s * 16);
    };

    float acc[4][4][4];
    #pragma unroll
    for (int a = 0; a < 4; a++)
        #pragma unroll
        for (int b = 0; b < 4; b++)
            #pragma unroll
            for (int e = 0; e < 4; e++) acc[a][b][e] = 0.f;

    const int l4r = lane >> 2;        // 0..7
    const int l4c = lane & 3;         // 0..3

    auto compute_chunk = [&](int buf) {
        const uint32_t* As = (const uint32_t*)(smem + buf * BUFB);
        const uint32_t* Bs = (const uint32_t*)(smem + buf * BUFB + OPB);
        #pragma unroll
        for (int ks = 0; ks < 4; ks++) {
            const int k0 = ks * 8;
            uint32_t af[4][4], bf[4][2];
            #pragma unroll
            for (int mt = 0; mt < 4; mt++) {
                const uint32_t* ap = As + (wm * 64 + mt * 16 + l4r) * RS + k0 + l4c;
                af[mt][0] = ap[0];
                af[mt][1] = ap[8 * RS];
                af[mt][2] = ap[4];
                af[mt][3] = ap[8 * RS + 4];
            }
            #pragma unroll
            for (int nt = 0; nt < 4; nt++) {
                const uint32_t* bp = Bs + (wn * 32 + nt * 8 + l4r) * RS + k0 + l4c;
                bf[nt][0] = bp[0];
                bf[nt][1] = bp[4];
            }
            #pragma unroll
            for (int mt = 0; mt < 4; mt++)
                #pragma unroll
                for (int nt = 0; nt < 4; nt++) MMA1688(acc[mt][nt], af[mt], bf[nt]);
        }
    };

    load_chunk(0, 0);
    CP_COMMIT();
    for (int c = 0; c < NCH; c++) {
        const int buf = c & 1;
        if (c + 1 < NCH) { load_chunk(c + 1, buf ^ 1); CP_COMMIT(); CP_WAIT1(); }
        else CP_WAIT0();
        __syncthreads();
        compute_chunk(buf);
        __syncthreads();
    }

    // ---- epilogue: dist + hard-neg mins + staged global writes ----
    float* sD = (float*)smem;    // [128][129], overlays buffers
    const float* sqi = (const float*)(smem + SM_SQI);
    const float* sqj = (const float*)(smem + SM_SQJ);
    const ulonglong2* smi = (const ulonglong2*)(smem + SM_MI);
    const ulonglong2* smj = (const ulonglong2*)(smem + SM_MJ);

    float rmin[4][2], cmin[4][2];
    #pragma unroll
    for (int a = 0; a < 4; a++) { rmin[a][0] = rmin[a][1] = 1e9f; cmin[a][0] = cmin[a][1] = 1e9f; }

    #pragma unroll
    for (int mt = 0; mt < 4; mt++)
        #pragma unroll
        for (int nt = 0; nt < 4; nt++)
            #pragma unroll
            for (int e = 0; e < 4; e++) {
                int m = wm * 64 + mt * 16 + (lane >> 2) + (e >> 1) * 8;
                int n = wn * 32 + nt * 8 + (lane & 3) * 2 + (e & 1);
                float d2 = sqi[m] + sqj[n] - 2.f * acc[mt][nt][e];
                float d = sqrtf(fmaxf(d2, 0.f));
                sD[m * 129 + n] = d;
                ulonglong2 ma = smi[m], mb = smj[n];
                int inter = __popcll(ma.x & mb.x) + __popcll(ma.y & mb.y);
                if (inter == 0) {
                    rmin[mt][e >> 1] = fminf(rmin[mt][e >> 1], d);
                    cmin[nt][e & 1] = fminf(cmin[nt][e & 1], d);
                }
            }

    // row-side hard-neg: reduce over lane&3 (same m)
    #pragma unroll
    for (int mt = 0; mt < 4; mt++)
        #pragma unroll
        for (int hh = 0; hh < 2; hh++) {
            float v = rmin[mt][hh];
            v = fminf(v, __shfl_xor_sync(0xFFFFFFFFu, v, 1));
            v = fminf(v, __shfl_xor_sync(0xFFFFFFFFu, v, 2));
            if ((lane & 3) == 0 && v < 1e9f) {
                int m = wm * 64 + mt * 16 + (lane >> 2) + hh * 8;
                atomicMin(&g_hardneg[by * BM + m], __float_as_uint(v));
            }
        }
    // col-side hard-neg (off-diagonal only): reduce over lane>>2 (same n)
    if (!diag) {
        #pragma unroll
        for (int nt = 0; nt < 4; nt++)
            #pragma unroll
            for (int b2 = 0; b2 < 2; b2++) {
                float v = cmin[nt][b2];
                v = fminf(v, __shfl_xor_sync(0xFFFFFFFFu, v, 4));
                v = fminf(v, __shfl_xor_sync(0xFFFFFFFFu, v, 8));
                v = fminf(v, __shfl_xor_sync(0xFFFFFFFFu, v, 16));
                if (lane < 4 && v < 1e9f) {
                    int n = wn * 32 + nt * 8 + (lane & 3) * 2 + b2;
                    atomicMin(&g_hardneg[bx * BM + n], __float_as_uint(v));
                }
            }
    }

    __syncthreads();
    const int cl = tid & 127;
    const int rh = tid >> 7;
    #pragma unroll 4
    for (int r2 = 0; r2 < 64; r2++) {
        int r = r2 * 2 + rh;
        g_dist[(size_t)(by * BM + r) * BB + bx * BM + cl] = sD[r * 129 + cl];
    }
    if (!diag) {
        #pragma unroll 4
        for (int r2 = 0; r2 < 64; r2++) {
            int c2 = r2 * 2 + rh;
            g_dist[(size_t)(bx * BM + c2) * BB + by * BM + cl] = sD[cl * 129 + c2];
        }
    }
}

// ---- 4) per-row weighted hinge over positives (4 anchors per block) ----
__global__ __launch_bounds__(256) void rowloss_kernel() {
    const int i0 = blockIdx.x * 4;
    const int t = threadIdx.x;
    __shared__ float rcp[176];
    for (int k = t; k < 176; k += 256) rcp[k] = 1.f / ((float)k + 1e-8f);

    float h[4];
    int si[4];
    ulonglong2 mi[4];
    #pragma unroll
    for (int a = 0; a < 4; a++) {
        h[a] = __uint_as_float(g_hardneg[i0 + a]);
        mi[a] = g_m[i0 + a];
        si[a] = g_si[i0 + a];
    }
    __syncthreads();

    float acc[4] = {0.f, 0.f, 0.f, 0.f};
    int cnt[4] = {0, 0, 0, 0};
    int ang[4] = {0, 0, 0, 0};

    for (int j0 = t * 4; j0 < BB; j0 += 1024) {
        ulonglong2 mj[4];
        #pragma unroll
        for (int u = 0; u < 4; u++) mj[u] = g_m[j0 + u];
        int4 sj4 = *(const int4*)(g_si + j0);
        int sj[4] = {sj4.x, sj4.y, sj4.z, sj4.w};
        #pragma unroll
        for (int a = 0; a < 4; a++) {
            float4 d4 = *(const float4*)(g_dist + (size_t)(i0 + a) * BB + j0);
            float dv[4] = {d4.x, d4.y, d4.z, d4.w};
            #pragma unroll
            for (int u = 0; u < 4; u++) {
                int inter = __popcll(mi[a].x & mj[u].x) + __popcll(mi[a].y & mj[u].y);
                if (inter == 0) {
                    ang[a] = 1;
                } else if (j0 + u != i0 + a) {
                    float jac = (float)inter * rcp[si[a] + sj[u] - inter];
                    acc[a] += fmaxf(dv[u] - h[a] + MARGIN, 0.f) * jac;
                    cnt[a]++;
                }
            }
        }
    }

    #pragma unroll
    for (int a = 0; a < 4; a++)
        #pragma unroll
        for (int o = 16; o > 0; o >>= 1) {
            acc[a] += __shfl_xor_sync(0xFFFFFFFFu, acc[a], o);
            cnt[a] += __shfl_xor_sync(0xFFFFFFFFu, cnt[a], o);
            ang[a] |= __shfl_xor_sync(0xFFFFFFFFu, ang[a], o);
        }
    __shared__ float sacc[8][4];
    __shared__ int scnt[8][4], sneg[8][4];
    if ((t & 31) == 0) {
        #pragma unroll
        for (int a = 0; a < 4; a++) {
            sacc[t >> 5][a] = acc[a];
            scnt[t >> 5][a] = cnt[a];
            sneg[t >> 5][a] = ang[a];
        }
    }
    __syncthreads();
    if (t < 4) {
        float av = 0.f; int c = 0, n = 0;
        #pragma unroll
        for (int w = 0; w < 8; w++) { av += sacc[w][t]; c += scnt[w][t]; n |= sneg[w][t]; }
        if (c > 0 && n) {
            atomicAdd(&g_loss_sum, av / (float)c);
            atomicAdd(&g_valid_cnt, 1.f);
        }
    }
}

// ---- 5) finalize ----
__global__ void finalize_kernel(float* out, int n) {
    if (threadIdx.x == 0 && blockIdx.x == 0) {
        out[0] = g_loss_sum / (g_valid_cnt + 1e-8f);
        for (int k = 1; k < n; k++) out[k] = 0.f;
    }
}

extern "C" void kernel_launch(void* const* d_in, const int* in_sizes, int n_in,
                              void* d_out, int out_size) {
    const float* emb = (const float*)d_in[0];
    const float* labels = (const float*)d_in[1];

    static int configured = 0;
    if (!configured) {
        cudaFuncSetAttribute(gemm_tc_kernel,
                             cudaFuncAttributeMaxDynamicSharedMemorySize, SM_TOT);
        configured = 1;
    }

    prep_kernel<<<(BB + 255) / 256, 256>>>(labels);
    normalize_kernel<<<BB, 128>>>(emb);
    gemm_tc_kernel<<<NTRI, 256, SM_TOT>>>();
    rowloss_kernel<<<BB / 4, 256>>>();
    finalize_kernel<<<1, 32>>>((float*)d_out, out_size);
}

// round 7
// speedup vs baseline: 1.4974x; 1.4974x over previous
#include <cuda_runtime.h>
#include <cuda_fp16.h>
#include <cstdint>
#include <math.h>

#define BB 8192
#define DD 512
#define CC 80
#define MARGIN 0.3f

#define BM 128
#define NTILE (BB / BM)                  // 64
#define NTRI  (NTILE * (NTILE + 1) / 2)  // 2080
#define BK 64                            // fp16 K-chunk
#define NCH (DD / BK)                    // 8

// smem layout (bytes)
#define RSB   144                        // padded row stride (64 fp16 =128B +16 pad)
#define OPB   (128 * RSB)                // 18432 per operand
#define BUFB  (2 * OPB)                  // 36864 per buffer (A,B)
#define SM_SQI 73728
#define SM_SQJ 74240
#define SM_MI  74752
#define SM_MJ  76800
#define SM_TOT 78848                     // sD[128*129*4B]=66048 overlays buffers

// ---- device scratch ----
__device__ __half g_eh[(size_t)BB * DD];       // fp16 normalized embeddings
__device__ float g_sq[BB];
__device__ ulonglong2 g_m[BB];
__device__ float g_s[BB];
__device__ float g_dist[(size_t)BB * BB];
__device__ unsigned g_hardneg[BB];
__device__ float g_loss_sum;
__device__ float g_valid_cnt;

// ---- PTX helpers (baseline ISA only) ----
__device__ __forceinline__ uint32_t smem_u32(const void* p) {
    uint32_t a;
    asm("{ .reg .u64 t; cvta.to.shared.u64 t, %1; cvt.u32.u64 %0, t; }" : "=r"(a) : "l"(p));
    return a;
}
#define CP_ASYNC16(dst, src) \
    asm volatile("cp.async.cg.shared.global [%0], [%1], 16;" :: "r"(dst), "l"(src))
#define CP_COMMIT() asm volatile("cp.async.commit_group;" ::: "memory")
#define CP_WAIT1()  asm volatile("cp.async.wait_group 1;" ::: "memory")
#define CP_WAIT0()  asm volatile("cp.async.wait_group 0;" ::: "memory")

#define LDSM_X4(r, a) \
    asm volatile("ldmatrix.sync.aligned.m8n8.x4.shared.b16 {%0,%1,%2,%3}, [%4];" \
        : "=r"((r)[0]), "=r"((r)[1]), "=r"((r)[2]), "=r"((r)[3]) : "r"(a))
#define LDSM_X2(r, a) \
    asm volatile("ldmatrix.sync.aligned.m8n8.x2.shared.b16 {%0,%1}, [%2];" \
        : "=r"((r)[0]), "=r"((r)[1]) : "r"(a))
#define MMA16816(d, a, b) \
    asm volatile("mma.sync.aligned.m16n8k16.row.col.f32.f16.f16.f32 " \
        "{%0,%1,%2,%3}, {%4,%5,%6,%7}, {%8,%9}, {%0,%1,%2,%3};" \
        : "+f"((d)[0]), "+f"((d)[1]), "+f"((d)[2]), "+f"((d)[3]) \
        : "r"((a)[0]), "r"((a)[1]), "r"((a)[2]), "r"((a)[3]), "r"((b)[0]), "r"((b)[1]))

// ---- 1) reset accumulators + label bitmasks ----
__global__ void prep_kernel(const float* __restrict__ labels) {
    int i = blockIdx.x * blockDim.x + threadIdx.x;
    if (i == 0) { g_loss_sum = 0.f; g_valid_cnt = 0.f; }
    if (i < BB) {
        const float* lr = labels + (size_t)i * CC;
        unsigned long long m0 = 0ull, m1 = 0ull;
        #pragma unroll
        for (int c = 0; c < 64; c++)
            if (lr[c] != 0.f) m0 |= (1ull << c);
        #pragma unroll
        for (int c = 64; c < CC; c++)
            if (lr[c] != 0.f) m1 |= (1ull << (c - 64));
        g_m[i] = make_ulonglong2(m0, m1);
        g_s[i] = (float)(__popcll(m0) + __popcll(m1));
        g_hardneg[i] = __float_as_uint(1e9f);
    }
}

// ---- 2) normalize + fp16 round ----
__global__ __launch_bounds__(128) void normalize_kernel(const float* __restrict__ emb) {
    int row = blockIdx.x;
    int t = threadIdx.x;
    const float4* in = (const float4*)(emb + (size_t)row * DD);
    float4 v = in[t];
    float ss = v.x * v.x + v.y * v.y + v.z * v.z + v.w * v.w;
    #pragma unroll
    for (int o = 16; o > 0; o >>= 1) ss += __shfl_xor_sync(0xFFFFFFFFu, ss, o);
    __shared__ float red[4];
    if ((t & 31) == 0) red[t >> 5] = ss;
    __syncthreads();
    float tot = red[0] + red[1] + red[2] + red[3];
    float inv = 1.f / fmaxf(sqrtf(tot), 1e-12f);
    __half hh[4];
    hh[0] = __float2half_rn(v.x * inv);
    hh[1] = __float2half_rn(v.y * inv);
    hh[2] = __float2half_rn(v.z * inv);
    hh[3] = __float2half_rn(v.w * inv);
    *(uint2*)(g_eh + (size_t)row * DD + t * 4) = *(uint2*)hh;
    if (t == 0) g_sq[row] = tot * inv * inv;
}

// ---- 3) fp16 single-pass mma.sync Gram GEMM over triangular tiles ----
__global__ __launch_bounds__(256, 2) void gemm_tc_kernel() {
    extern __shared__ __align__(1024) char smem[];
    const uint32_t sb = smem_u32(smem);
    const int tid = threadIdx.x;
    const int wid = tid >> 5;
    const int lane = tid & 31;
    const int wm = wid >> 2;         // 0..1 -> rows wm*64
    const int wn = wid & 3;          // 0..3 -> cols wn*32

    // triangular tile map (by <= bx)
    const int t = blockIdx.x;
    int p = (int)((sqrt(8.0 * t + 1.0) - 1.0) * 0.5);
    while ((p * (p + 1)) / 2 > t) p--;
    while (((p + 1) * (p + 2)) / 2 <= t) p++;
    const int bx = p;
    const int by = t - (p * (p + 1)) / 2;
    const bool diag = (bx == by);

    // stage per-row/col metadata (region disjoint from pipeline buffers)
    if (tid < 128) {
        int gi = by * BM + tid, gj = bx * BM + tid;
        ((float*)(smem + SM_SQI))[tid] = g_sq[gi];
        ((float*)(smem + SM_SQJ))[tid] = g_sq[gj];
        ((ulonglong2*)(smem + SM_MI))[tid] = g_m[gi];
        ((ulonglong2*)(smem + SM_MJ))[tid] = g_m[gj];
    }

    // loader: threads 0-127 -> A rows, 128-255 -> B rows; 8 x 16B per row-chunk
    const int lrow = tid & 127;
    const int lop = tid >> 7;                    // 0=A, 1=B
    const char* src_row = (const char*)(g_eh + (size_t)(((lop ? bx : by) * BM) + lrow) * DD);

    auto load_chunk = [&](int c, int buf) {
        uint32_t dst = sb + buf * BUFB + lop * OPB + lrow * RSB;
        const char* src = src_row + c * (BK * 2);
        #pragma unroll
        for (int s = 0; s < 8; s++)
            CP_ASYNC16(dst + s * 16, src + s * 16);
    };

    float acc[4][4][4];
    #pragma unroll
    for (int a = 0; a < 4; a++)
        #pragma unroll
        for (int b = 0; b < 4; b++)
            #pragma unroll
            for (int e = 0; e < 4; e++) acc[a][b][e] = 0.f;

    auto compute_chunk = [&](int buf) {
        const uint32_t ab = sb + buf * BUFB;
        const uint32_t bbse = ab + OPB;
        const int l16 = lane & 15;
        #pragma unroll
        for (int ks = 0; ks < 4; ks++) {
            uint32_t af[4][4], bf[4][2];
            const int aoff = (wm * 64 + l16) * RSB + ks * 32 + (lane >> 4) * 16;
            #pragma unroll
            for (int mt = 0; mt < 4; mt++)
                LDSM_X4(af[mt], ab + aoff + mt * 16 * RSB);
            const int boff = (wn * 32 + (l16 & 7)) * RSB + ks * 32 + (l16 >> 3) * 16;
            #pragma unroll
            for (int nt = 0; nt < 4; nt++)
                LDSM_X2(bf[nt], bbse + boff + nt * 8 * RSB);
            #pragma unroll
            for (int mt = 0; mt < 4; mt++)
                #pragma unroll
                for (int nt = 0; nt < 4; nt++)
                    MMA16816(acc[mt][nt], af[mt], bf[nt]);
        }
    };

    load_chunk(0, 0);
    CP_COMMIT();
    for (int c = 0; c < NCH; c++) {
        const int buf = c & 1;
        if (c + 1 < NCH) { load_chunk(c + 1, buf ^ 1); CP_COMMIT(); CP_WAIT1(); }
        else CP_WAIT0();
        __syncthreads();
        compute_chunk(buf);
        __syncthreads();
    }

    // ---- epilogue: dist + hard-neg mins + staged global writes ----
    float* sD = (float*)smem;    // [128][129], overlays buffers
    const float* sqi = (const float*)(smem + SM_SQI);
    const float* sqj = (const float*)(smem + SM_SQJ);
    const ulonglong2* smi = (const ulonglong2*)(smem + SM_MI);
    const ulonglong2* smj = (const ulonglong2*)(smem + SM_MJ);

    float rmin[4][2], cmin[4][2];
    #pragma unroll
    for (int a = 0; a < 4; a++) { rmin[a][0] = rmin[a][1] = 1e9f; cmin[a][0] = cmin[a][1] = 1e9f; }

    #pragma unroll
    for (int mt = 0; mt < 4; mt++)
        #pragma unroll
        for (int nt = 0; nt < 4; nt++)
            #pragma unroll
            for (int e = 0; e < 4; e++) {
                int m = wm * 64 + mt * 16 + (lane >> 2) + (e >> 1) * 8;
                int n = wn * 32 + nt * 8 + (lane & 3) * 2 + (e & 1);
                float d2 = sqi[m] + sqj[n] - 2.f * acc[mt][nt][e];
                float d = sqrtf(fmaxf(d2, 0.f));
                sD[m * 129 + n] = d;
                ulonglong2 ma = smi[m], mb = smj[n];
                int inter = __popcll(ma.x & mb.x) + __popcll(ma.y & mb.y);
                if (inter == 0) {
                    rmin[mt][e >> 1] = fminf(rmin[mt][e >> 1], d);
                    cmin[nt][e & 1] = fminf(cmin[nt][e & 1], d);
                }
            }

    // row-side hard-neg: reduce over lane&3 (same m)
    #pragma unroll
    for (int mt = 0; mt < 4; mt++)
        #pragma unroll
        for (int hh = 0; hh < 2; hh++) {
            float v = rmin[mt][hh];
            v = fminf(v, __shfl_xor_sync(0xFFFFFFFFu, v, 1));
            v = fminf(v, __shfl_xor_sync(0xFFFFFFFFu, v, 2));
            if ((lane & 3) == 0 && v < 1e9f) {
                int m = wm * 64 + mt * 16 + (lane >> 2) + hh * 8;
                atomicMin(&g_hardneg[by * BM + m], __float_as_uint(v));
            }
        }
    // col-side hard-neg (off-diagonal only): reduce over lane>>2 (same n)
    if (!diag) {
        #pragma unroll
        for (int nt = 0; nt < 4; nt++)
            #pragma unroll
            for (int b2 = 0; b2 < 2; b2++) {
                float v = cmin[nt][b2];
                v = fminf(v, __shfl_xor_sync(0xFFFFFFFFu, v, 4));
                v = fminf(v, __shfl_xor_sync(0xFFFFFFFFu, v, 8));
                v = fminf(v, __shfl_xor_sync(0xFFFFFFFFu, v, 16));
                if (lane < 4 && v < 1e9f) {
                    int n = wn * 32 + nt * 8 + (lane & 3) * 2 + b2;
                    atomicMin(&g_hardneg[bx * BM + n], __float_as_uint(v));
                }
            }
    }

    __syncthreads();
    const int cl = tid & 127;
    const int rh = tid >> 7;
    #pragma unroll 4
    for (int r2 = 0; r2 < 64; r2++) {
        int r = r2 * 2 + rh;
        g_dist[(size_t)(by * BM + r) * BB + bx * BM + cl] = sD[r * 129 + cl];
    }
    if (!diag) {
        #pragma unroll 4
        for (int r2 = 0; r2 < 64; r2++) {
            int c2 = r2 * 2 + rh;
            g_dist[(size_t)(bx * BM + c2) * BB + by * BM + cl] = sD[cl * 129 + c2];
        }
    }
}

// ---- 4) per-row weighted hinge over positives (4 anchors per block) ----
__global__ __launch_bounds__(256) void rowloss_kernel() {
    const int i0 = blockIdx.x * 4;
    const int t = threadIdx.x;
    float h[4], si[4];
    ulonglong2 mi[4];
    #pragma unroll
    for (int a = 0; a < 4; a++) {
        h[a] = __uint_as_float(g_hardneg[i0 + a]);
        mi[a] = g_m[i0 + a];
        si[a] = g_s[i0 + a];
    }
    float acc[4] = {0.f, 0.f, 0.f, 0.f};
    int cnt[4] = {0, 0, 0, 0};
    int ang[4] = {0, 0, 0, 0};

    for (int j0 = t * 4; j0 < BB; j0 += 1024) {
        ulonglong2 mj[4];
        #pragma unroll
        for (int u = 0; u < 4; u++) mj[u] = g_m[j0 + u];
        float4 sj4 = *(const float4*)(g_s + j0);
        float sj[4] = {sj4.x, sj4.y, sj4.z, sj4.w};
        #pragma unroll
        for (int a = 0; a < 4; a++) {
            float4 d4 = *(const float4*)(g_dist + (size_t)(i0 + a) * BB + j0);
            float dv[4] = {d4.x, d4.y, d4.z, d4.w};
            #pragma unroll
            for (int u = 0; u < 4; u++) {
                int inter = __popcll(mi[a].x & mj[u].x) + __popcll(mi[a].y & mj[u].y);
                if (inter == 0) {
                    ang[a] = 1;
                } else if (j0 + u != i0 + a) {
                    float jac = __fdividef((float)inter, si[a] + sj[u] - (float)inter + 1e-8f);
                    acc[a] += fmaxf(dv[u] - h[a] + MARGIN, 0.f) * jac;
                    cnt[a]++;
                }
            }
        }
    }

    #pragma unroll
    for (int a = 0; a < 4; a++)
        #pragma unroll
        for (int o = 16; o > 0; o >>= 1) {
            acc[a] += __shfl_xor_sync(0xFFFFFFFFu, acc[a], o);
            cnt[a] += __shfl_xor_sync(0xFFFFFFFFu, cnt[a], o);
            ang[a] |= __shfl_xor_sync(0xFFFFFFFFu, ang[a], o);
        }
    __shared__ float sacc[8][4];
    __shared__ int scnt[8][4], sneg[8][4];
    if ((t & 31) == 0) {
        #pragma unroll
        for (int a = 0; a < 4; a++) {
            sacc[t >> 5][a] = acc[a];
            scnt[t >> 5][a] = cnt[a];
            sneg[t >> 5][a] = ang[a];
        }
    }
    __syncthreads();
    if (t < 4) {
        float av = 0.f; int c = 0, n = 0;
        #pragma unroll
        for (int w = 0; w < 8; w++) { av += sacc[w][t]; c += scnt[w][t]; n |= sneg[w][t]; }
        if (c > 0 && n) {
            atomicAdd(&g_loss_sum, av / (float)c);
            atomicAdd(&g_valid_cnt, 1.f);
        }
    }
}

// ---- 5) finalize ----
__global__ void finalize_kernel(float* out, int n) {
    if (threadIdx.x == 0 && blockIdx.x == 0) {
        out[0] = g_loss_sum / (g_valid_cnt + 1e-8f);
        for (int k = 1; k < n; k++) out[k] = 0.f;
    }
}

extern "C" void kernel_launch(void* const* d_in, const int* in_sizes, int n_in,
                              void* d_out, int out_size) {
    const float* emb = (const float*)d_in[0];
    const float* labels = (const float*)d_in[1];

    static int configured = 0;
    if (!configured) {
        cudaFuncSetAttribute(gemm_tc_kernel,
                             cudaFuncAttributeMaxDynamicSharedMemorySize, SM_TOT);
        configured = 1;
    }

    prep_kernel<<<(BB + 255) / 256, 256>>>(labels);
    normalize_kernel<<<BB, 128>>>(emb);
    gemm_tc_kernel<<<NTRI, 256, SM_TOT>>>();
    rowloss_kernel<<<BB / 4, 256>>>();
    finalize_kernel<<<1, 32>>>((float*)d_out, out_size);
}